// round 2
// baseline (speedup 1.0000x reference)
#include <cuda_runtime.h>
#include <cstdint>
#include <cstddef>

// Problem constants (fixed by reference setup_inputs)
#define BATCH  4
#define LQN    4096
#define LKN    4096
#define EMB    1024
#define NH     16
#define HD     64
#define BHN    (BATCH*NH)      // 64
#define NCHUNK 8
#define CHUNKK (LKN/NCHUNK)    // 512
#define KT     32              // k-rows per smem tile in phase 1
#define QT     256             // q-rows per CTA in phase 2
#define SQ_STRIDE 260          // padded (multiple of 4 for 16B-aligned rows)

// Scratch (static __device__ — no allocation)
__device__ float g_kvp[(size_t)NCHUNK*BHN*HD*HD];  // 8 MB partial kv
__device__ float g_ksp[(size_t)NCHUNK*BHN*HD];     // partial ksum
__device__ float g_kv [(size_t)BHN*HD*HD];         // 1 MB reduced kv
__device__ float g_ks [(size_t)BHN*HD];            // reduced ksum

// ---------------- helpers ----------------
typedef unsigned long long u64;

__device__ __forceinline__ float phi_sig(float x){
    // sigmoid(0.6053*x - 4.102) = 1 / (1 + exp2(-0.8732633*x + 5.9179351))
    float t, r;
    float a = fmaf(x, -0.8732633f, 5.9179351f);
    asm("ex2.approx.ftz.f32 %0, %1;" : "=f"(t) : "f"(a));
    asm("rcp.approx.ftz.f32 %0, %1;" : "=f"(r) : "f"(1.0f + t));
    return r;
}
__device__ __forceinline__ u64 pk2(float a, float b){
    u64 r; asm("mov.b64 %0, {%1,%2};" : "=l"(r) : "f"(a), "f"(b)); return r;
}
__device__ __forceinline__ void upk2(u64 v, float& a, float& b){
    asm("mov.b64 {%0,%1}, %2;" : "=f"(a), "=f"(b) : "l"(v));
}
__device__ __forceinline__ u64 fma2(u64 a, u64 b, u64 c){
    u64 d; asm("fma.rn.f32x2 %0, %1, %2, %3;" : "=l"(d) : "l"(a), "l"(b), "l"(c)); return d;
}
__device__ __forceinline__ u64 mul2(u64 a, u64 b){
    u64 d; asm("mul.rn.f32x2 %0, %1, %2;" : "=l"(d) : "l"(a), "l"(b)); return d;
}
__device__ __forceinline__ float rcpf(float x){
    float r; asm("rcp.approx.ftz.f32 %0, %1;" : "=f"(r) : "f"(x)); return r;
}

// ---------------- Phase 1: kv partials = phi(K)^T @ V per (b,h,chunk) ----------------
// grid (BHN, NCHUNK), 256 threads. Thread (dg,eg) in 16x16 owns 4d x 4e of kv.
__global__ void __launch_bounds__(256) la_phase1(const float* __restrict__ K,
                                                 const float* __restrict__ V){
    __shared__ float sK[KT][HD];
    __shared__ float sV[KT][HD];
    const int tid = threadIdx.x;
    const int bh  = blockIdx.x;
    const int ck  = blockIdx.y;
    const int b   = bh >> 4;
    const int h   = bh & 15;
    const int k0  = ck * CHUNKK;

    const float* Kb = K + (size_t)b*LKN*EMB + (size_t)h*HD;
    const float* Vb = V + (size_t)b*LKN*EMB + (size_t)h*HD;

    const int lrow = tid >> 4;   // 0..15  (loads rows lrow, lrow+16)
    const int lc4  = tid & 15;   // float4 column index
    const int dg   = tid >> 4;   // 0..15 -> d = 4*dg..4*dg+3
    const int eg   = tid & 15;   // 0..15 -> e = 4*eg..4*eg+3

    u64 acc[4][2];
    float ks[4];
    #pragma unroll
    for(int i=0;i<4;i++){ acc[i][0]=0ull; acc[i][1]=0ull; ks[i]=0.0f; }

    float4 pk_[2], pv_[2];
    #pragma unroll
    for(int i=0;i<2;i++){
        int r = lrow + i*16;
        pk_[i] = *(const float4*)(Kb + (size_t)(k0 + r)*EMB + lc4*4);
        pv_[i] = *(const float4*)(Vb + (size_t)(k0 + r)*EMB + lc4*4);
    }

    const int NT = CHUNKK / KT;   // 16 tiles
    for(int t=0; t<NT; t++){
        __syncthreads();
        #pragma unroll
        for(int i=0;i<2;i++){
            int r = lrow + i*16;
            sK[r][lc4*4+0] = phi_sig(pk_[i].x);
            sK[r][lc4*4+1] = phi_sig(pk_[i].y);
            sK[r][lc4*4+2] = phi_sig(pk_[i].z);
            sK[r][lc4*4+3] = phi_sig(pk_[i].w);
            *(float4*)&sV[r][lc4*4] = pv_[i];
        }
        __syncthreads();
        if(t+1 < NT){
            #pragma unroll
            for(int i=0;i<2;i++){
                int r = lrow + i*16 + (t+1)*KT;
                pk_[i] = *(const float4*)(Kb + (size_t)(k0 + r)*EMB + lc4*4);
                pv_[i] = *(const float4*)(Vb + (size_t)(k0 + r)*EMB + lc4*4);
            }
        }
        #pragma unroll 8
        for(int kk=0; kk<KT; kk++){
            float4 a4 = *(const float4*)&sK[kk][dg*4];
            float4 v4 = *(const float4*)&sV[kk][eg*4];
            u64 vlo = pk2(v4.x, v4.y);
            u64 vhi = pk2(v4.z, v4.w);
            float a_[4] = {a4.x, a4.y, a4.z, a4.w};
            #pragma unroll
            for(int i=0;i<4;i++){
                u64 pa = pk2(a_[i], a_[i]);
                acc[i][0] = fma2(pa, vlo, acc[i][0]);
                acc[i][1] = fma2(pa, vhi, acc[i][1]);
            }
            if(eg == 0){
                ks[0] += a_[0]; ks[1] += a_[1]; ks[2] += a_[2]; ks[3] += a_[3];
            }
        }
    }

    // write partial kv tile
    float* dst = g_kvp + ((size_t)(ck*BHN + bh)*HD + dg*4)*HD + eg*4;
    #pragma unroll
    for(int i=0;i<4;i++){
        float4 o;
        upk2(acc[i][0], o.x, o.y);
        upk2(acc[i][1], o.z, o.w);
        *(float4*)(dst + (size_t)i*HD) = o;
    }
    if(eg == 0){
        float* kd = g_ksp + (size_t)(ck*BHN + bh)*HD + dg*4;
        #pragma unroll
        for(int i=0;i<4;i++) kd[i] = ks[i];
    }
}

// ---------------- Reduce partials ----------------
__global__ void __launch_bounds__(256) la_reduce(){
    const int bh = blockIdx.x;
    const int tid = threadIdx.x;
    for(int idx = tid; idx < HD*HD; idx += 256){
        float s = 0.0f;
        #pragma unroll
        for(int c=0;c<NCHUNK;c++)
            s += g_kvp[(size_t)(c*BHN + bh)*HD*HD + idx];
        g_kv[(size_t)bh*HD*HD + idx] = s;
    }
    if(tid < HD){
        float s = 0.0f;
        #pragma unroll
        for(int c=0;c<NCHUNK;c++)
            s += g_ksp[(size_t)(c*BHN + bh)*HD + tid];
        g_ks[(size_t)bh*HD + tid] = s;
    }
}

// ---------------- Phase 2: out = (phi(Q)@kv) / (phi(Q)@ksum) ----------------
// grid 1024 = 64 heads x 16 q-tiles of 256 rows. 256 threads.
// Thread (qg 0..31, eg 0..7) owns 8 q-rows x 8 e-cols.
extern __shared__ float smem2[];
__global__ void __launch_bounds__(256, 2) la_phase2(const float* __restrict__ Q,
                                                    float* __restrict__ out){
    float* sQ  = smem2;                       // [HD][SQ_STRIDE] transposed phi(Q)
    float* sKV = smem2 + HD*SQ_STRIDE;        // [HD][HD]
    float* sKs = sKV + HD*HD;                 // [HD]

    const int tid = threadIdx.x;
    const int bh  = blockIdx.x >> 4;
    const int qt  = blockIdx.x & 15;
    const int b   = bh >> 4;
    const int h   = bh & 15;
    const int q0  = qt * QT;

    // load kv + ksum
    const float4* kvsrc = (const float4*)(g_kv + (size_t)bh*HD*HD);
    #pragma unroll
    for(int i=0;i<4;i++)
        ((float4*)sKV)[tid + i*256] = kvsrc[tid + i*256];
    if(tid < HD) sKs[tid] = g_ks[(size_t)bh*HD + tid];

    // load phi(Q) transposed: [d][q]
    const int lr = tid >> 4, c4 = tid & 15;
    const float* Qb = Q + ((size_t)b*LQN + q0)*EMB + (size_t)h*HD;
    #pragma unroll
    for(int p=0;p<16;p++){
        int row = p*16 + lr;
        float4 v = *(const float4*)(Qb + (size_t)row*EMB + c4*4);
        sQ[(c4*4+0)*SQ_STRIDE + row] = phi_sig(v.x);
        sQ[(c4*4+1)*SQ_STRIDE + row] = phi_sig(v.y);
        sQ[(c4*4+2)*SQ_STRIDE + row] = phi_sig(v.z);
        sQ[(c4*4+3)*SQ_STRIDE + row] = phi_sig(v.w);
    }
    __syncthreads();

    const int qg = tid >> 3;    // 0..31
    const int eg = tid & 7;     // 0..7

    u64 acc[8][4];
    float den[8];
    #pragma unroll
    for(int q=0;q<8;q++){
        den[q] = 0.0f;
        #pragma unroll
        for(int j=0;j<4;j++) acc[q][j] = 0ull;
    }

    const float* aBase  = sQ  + qg*8;
    const float* kvBase = sKV + eg*8;

    #pragma unroll 8
    for(int d=0; d<HD; d++){
        float4 a0 = *(const float4*)(aBase + (size_t)d*SQ_STRIDE);
        float4 a1 = *(const float4*)(aBase + (size_t)d*SQ_STRIDE + 4);
        float4 kv0 = *(const float4*)(kvBase + (size_t)d*HD);
        float4 kv1 = *(const float4*)(kvBase + (size_t)d*HD + 4);
        float ksd = sKs[d];
        u64 kp[4] = { pk2(kv0.x,kv0.y), pk2(kv0.z,kv0.w),
                      pk2(kv1.x,kv1.y), pk2(kv1.z,kv1.w) };
        float a_[8] = {a0.x,a0.y,a0.z,a0.w,a1.x,a1.y,a1.z,a1.w};
        #pragma unroll
        for(int q=0;q<8;q++){
            u64 pa = pk2(a_[q], a_[q]);
            #pragma unroll
            for(int j=0;j<4;j++) acc[q][j] = fma2(pa, kp[j], acc[q][j]);
            den[q] = fmaf(a_[q], ksd, den[q]);
        }
    }

    // epilogue: divide + store
    float* ob = out + ((size_t)b*LQN + q0 + qg*8)*EMB + (size_t)h*HD + eg*8;
    #pragma unroll
    for(int q=0;q<8;q++){
        float rd = rcpf(den[q]);
        u64 pr = pk2(rd, rd);
        float4 o0, o1;
        u64 m0 = mul2(acc[q][0], pr);
        u64 m1 = mul2(acc[q][1], pr);
        u64 m2 = mul2(acc[q][2], pr);
        u64 m3 = mul2(acc[q][3], pr);
        upk2(m0, o0.x, o0.y); upk2(m1, o0.z, o0.w);
        upk2(m2, o1.x, o1.y); upk2(m3, o1.z, o1.w);
        *(float4*)(ob + (size_t)q*EMB)     = o0;
        *(float4*)(ob + (size_t)q*EMB + 4) = o1;
    }
}

// ---------------- launch ----------------
extern "C" void kernel_launch(void* const* d_in, const int* in_sizes, int n_in,
                              void* d_out, int out_size){
    const float* Q = (const float*)d_in[0];
    const float* K = (const float*)d_in[1];
    const float* V = (const float*)d_in[2];
    float* out = (float*)d_out;

    size_t smem2_bytes = (size_t)(HD*SQ_STRIDE + HD*HD + HD)*sizeof(float);
    cudaFuncSetAttribute(la_phase2, cudaFuncAttributeMaxDynamicSharedMemorySize,
                         (int)smem2_bytes);

    la_phase1<<<dim3(BHN, NCHUNK), 256>>>(K, V);
    la_reduce<<<BHN, 256>>>();
    la_phase2<<<BHN*16, 256, smem2_bytes>>>(Q, out);
}